// round 1
// baseline (speedup 1.0000x reference)
#include <cuda_runtime.h>

// ----------------------------------------------------------------------------
// Attention_53944789237811
//   keys    = LayerNorm(Y @ K) * g1 + b1          [B,S,H]
//   queries = LayerNorm(X @ Q) * g2 + b2          [B,S,H]
//   alpha   = softmax(queries @ keys^T / H)       [B,S,S]
//   out     = alpha @ Y                           [B,S,F]
// B=8, S=2048, F=H=1024. All fp32 this round (correctness baseline).
// ----------------------------------------------------------------------------

#define BM 128
#define BN 128
#define BK 8

// Scratch: __device__ globals (no cudaMalloc allowed).
__device__ float g_keys   [8ull * 2048 * 1024];   //  64 MB
__device__ float g_queries[8ull * 2048 * 1024];   //  64 MB
__device__ float g_alpha  [8ull * 2048 * 2048];   // 128 MB

// ----------------------------------------------------------------------------
// Tiled SGEMM: C[M,N] = A[M,K] * B  (B is [K,N] row-major, or [N,K] if TRANS_B)
// 128x128 block tile, BK=8, 256 threads, 8x8 per-thread micro-tile.
// Assumes M,N multiples of 128 and K multiple of 8 (true for all our shapes).
// blockIdx.z = batch, with per-batch strides sA/sB/sC.
// ----------------------------------------------------------------------------
template <bool TRANS_B>
__global__ __launch_bounds__(256) void sgemm_kernel(
    const float* __restrict__ A, const float* __restrict__ B,
    float* __restrict__ C,
    int M, int N, int Kd,
    long long sA, long long sB, long long sC)
{
    A += (long long)blockIdx.z * sA;
    B += (long long)blockIdx.z * sB;
    C += (long long)blockIdx.z * sC;

    __shared__ float As[BK][BM];
    __shared__ float Bs[BK][BN];

    const int tid = threadIdx.x;
    const int tx  = tid & 15;       // 0..15 (N direction)
    const int ty  = tid >> 4;       // 0..15 (M direction)
    const int row0 = blockIdx.y * BM;
    const int col0 = blockIdx.x * BN;

    // Loader mapping (K-innermost tiles, 1 float4 per thread)
    const int lrow = tid >> 1;          // 0..127
    const int lcol = (tid & 1) * 4;     // 0 or 4
    // Loader mapping for NN B tile ([BK x BN])
    const int bnrow = tid >> 5;         // 0..7
    const int bncol = (tid & 31) * 4;   // 0..124

    float acc[8][8];
#pragma unroll
    for (int i = 0; i < 8; i++)
#pragma unroll
        for (int j = 0; j < 8; j++) acc[i][j] = 0.f;

    for (int k0 = 0; k0 < Kd; k0 += BK) {
        // --- load A tile (transpose into As[k][m]) ---
        float4 av = *(const float4*)(A + (long long)(row0 + lrow) * Kd + (k0 + lcol));
        As[lcol + 0][lrow] = av.x;
        As[lcol + 1][lrow] = av.y;
        As[lcol + 2][lrow] = av.z;
        As[lcol + 3][lrow] = av.w;

        // --- load B tile into Bs[k][n] ---
        if (TRANS_B) {
            // B is [N, Kd] row-major
            float4 bv = *(const float4*)(B + (long long)(col0 + lrow) * Kd + (k0 + lcol));
            Bs[lcol + 0][lrow] = bv.x;
            Bs[lcol + 1][lrow] = bv.y;
            Bs[lcol + 2][lrow] = bv.z;
            Bs[lcol + 3][lrow] = bv.w;
        } else {
            // B is [Kd, N] row-major
            float4 bv = *(const float4*)(B + (long long)(k0 + bnrow) * N + (col0 + bncol));
            *(float4*)&Bs[bnrow][bncol] = bv;
        }
        __syncthreads();

#pragma unroll
        for (int kk = 0; kk < BK; kk++) {
            float a[8], b[8];
            *(float4*)&a[0] = *(const float4*)&As[kk][ty * 4];
            *(float4*)&a[4] = *(const float4*)&As[kk][64 + ty * 4];
            *(float4*)&b[0] = *(const float4*)&Bs[kk][tx * 4];
            *(float4*)&b[4] = *(const float4*)&Bs[kk][64 + tx * 4];
#pragma unroll
            for (int i = 0; i < 8; i++)
#pragma unroll
                for (int j = 0; j < 8; j++)
                    acc[i][j] += a[i] * b[j];
        }
        __syncthreads();
    }

#pragma unroll
    for (int i = 0; i < 8; i++) {
        const int r = row0 + ((i < 4) ? (ty * 4 + i) : (64 + ty * 4 + (i - 4)));
        float4 v0 = make_float4(acc[i][0], acc[i][1], acc[i][2], acc[i][3]);
        float4 v1 = make_float4(acc[i][4], acc[i][5], acc[i][6], acc[i][7]);
        *(float4*)(C + (long long)r * N + col0 + tx * 4)      = v0;
        *(float4*)(C + (long long)r * N + col0 + 64 + tx * 4) = v1;
    }
}

// ----------------------------------------------------------------------------
// LayerNorm in-place over rows of length 1024. One block (256 thr) per row.
// Biased variance (jnp.var default), eps = 1e-5.
// ----------------------------------------------------------------------------
__global__ __launch_bounds__(256) void layernorm_kernel(
    float* __restrict__ data,
    const float* __restrict__ gamma, const float* __restrict__ beta)
{
    const int H = 1024;
    float* row = data + (long long)blockIdx.x * H;
    const int t = threadIdx.x;
    const int lane = t & 31, wid = t >> 5;

    float v[4];
    float s = 0.f, q = 0.f;
#pragma unroll
    for (int i = 0; i < 4; i++) {
        v[i] = row[t + i * 256];
        s += v[i];
        q += v[i] * v[i];
    }
#pragma unroll
    for (int o = 16; o > 0; o >>= 1) {
        s += __shfl_xor_sync(0xffffffffu, s, o);
        q += __shfl_xor_sync(0xffffffffu, q, o);
    }
    __shared__ float ss[8], sq[8];
    if (lane == 0) { ss[wid] = s; sq[wid] = q; }
    __syncthreads();
    if (wid == 0) {
        float s2 = (lane < 8) ? ss[lane] : 0.f;
        float q2 = (lane < 8) ? sq[lane] : 0.f;
#pragma unroll
        for (int o = 4; o > 0; o >>= 1) {
            s2 += __shfl_xor_sync(0xffffffffu, s2, o);
            q2 += __shfl_xor_sync(0xffffffffu, q2, o);
        }
        if (lane == 0) { ss[0] = s2; sq[0] = q2; }
    }
    __syncthreads();
    const float mu  = ss[0] * (1.f / 1024.f);
    const float var = sq[0] * (1.f / 1024.f) - mu * mu;
    const float inv = rsqrtf(var + 1e-5f);
#pragma unroll
    for (int i = 0; i < 4; i++) {
        const int c = t + i * 256;
        row[c] = (v[i] - mu) * inv * gamma[c] + beta[c];
    }
}

// ----------------------------------------------------------------------------
// Softmax in-place over rows of length 2048, with pre-scale 1/1024.
// One block (256 thr) per row.
// ----------------------------------------------------------------------------
__global__ __launch_bounds__(256) void softmax_kernel(float* __restrict__ alpha)
{
    const int S = 2048;
    float* row = alpha + (long long)blockIdx.x * S;
    const int t = threadIdx.x;
    const int lane = t & 31, wid = t >> 5;
    const float scale = 1.0f / 1024.0f;

    __shared__ float sbuf[8];

    float v[8];
    float mx = -1e30f;
#pragma unroll
    for (int i = 0; i < 8; i++) {
        v[i] = row[t + i * 256] * scale;
        mx = fmaxf(mx, v[i]);
    }
#pragma unroll
    for (int o = 16; o > 0; o >>= 1)
        mx = fmaxf(mx, __shfl_xor_sync(0xffffffffu, mx, o));
    if (lane == 0) sbuf[wid] = mx;
    __syncthreads();
    if (wid == 0) {
        float m2 = (lane < 8) ? sbuf[lane] : -1e30f;
#pragma unroll
        for (int o = 4; o > 0; o >>= 1)
            m2 = fmaxf(m2, __shfl_xor_sync(0xffffffffu, m2, o));
        if (lane == 0) sbuf[0] = m2;
    }
    __syncthreads();
    mx = sbuf[0];
    __syncthreads();   // sbuf reused below

    float s = 0.f;
#pragma unroll
    for (int i = 0; i < 8; i++) {
        v[i] = expf(v[i] - mx);
        s += v[i];
    }
#pragma unroll
    for (int o = 16; o > 0; o >>= 1)
        s += __shfl_xor_sync(0xffffffffu, s, o);
    if (lane == 0) sbuf[wid] = s;
    __syncthreads();
    if (wid == 0) {
        float s2 = (lane < 8) ? sbuf[lane] : 0.f;
#pragma unroll
        for (int o = 4; o > 0; o >>= 1)
            s2 += __shfl_xor_sync(0xffffffffu, s2, o);
        if (lane == 0) sbuf[0] = s2;
    }
    __syncthreads();
    const float inv = 1.f / sbuf[0];
#pragma unroll
    for (int i = 0; i < 8; i++)
        row[t + i * 256] = v[i] * inv;
}

// ----------------------------------------------------------------------------
// kernel_launch: inputs in metadata order: X, Y, K, Q, g1, b1, g2, b2
// ----------------------------------------------------------------------------
extern "C" void kernel_launch(void* const* d_in, const int* in_sizes, int n_in,
                              void* d_out, int out_size)
{
    const float* X  = (const float*)d_in[0];
    const float* Y  = (const float*)d_in[1];
    const float* K  = (const float*)d_in[2];
    const float* Q  = (const float*)d_in[3];
    const float* g1 = (const float*)d_in[4];
    const float* b1 = (const float*)d_in[5];
    const float* g2 = (const float*)d_in[6];
    const float* b2 = (const float*)d_in[7];
    float* out = (float*)d_out;

    float *keys, *queries, *alpha;
    cudaGetSymbolAddress((void**)&keys,    g_keys);
    cudaGetSymbolAddress((void**)&queries, g_queries);
    cudaGetSymbolAddress((void**)&alpha,   g_alpha);

    const int B = 8, S = 2048, F = 1024, H = 1024;
    const long long sQK = (long long)S * H;  // per-batch stride for q/k
    const long long sAL = (long long)S * S;  // per-batch stride for alpha
    const long long sY  = (long long)S * F;  // per-batch stride for Y/out

    dim3 blk(256);

    // 1) projections: keys_raw = Y@K, queries_raw = X@Q   ([16384,1024]x[1024,1024])
    sgemm_kernel<false><<<dim3(H / BN, (B * S) / BM, 1), blk>>>(
        Y, K, keys, B * S, H, F, 0, 0, 0);
    sgemm_kernel<false><<<dim3(H / BN, (B * S) / BM, 1), blk>>>(
        X, Q, queries, B * S, H, F, 0, 0, 0);

    // 2) layernorms (in-place)
    layernorm_kernel<<<B * S, 256>>>(keys, g1, b1);
    layernorm_kernel<<<B * S, 256>>>(queries, g2, b2);

    // 3) logits: alpha[b] = queries[b] @ keys[b]^T   (NT, per batch)
    sgemm_kernel<true><<<dim3(S / BN, S / BM, B), blk>>>(
        queries, keys, alpha, S, S, H, sQK, sQK, sAL);

    // 4) softmax rows (scale 1/H applied inside)
    softmax_kernel<<<B * S, 256>>>(alpha);

    // 5) out[b] = alpha[b] @ Y[b]   (NN, per batch)
    sgemm_kernel<false><<<dim3(F / BN, S / BM, B), blk>>>(
        alpha, Y, out, S, F, S, sAL, sY, sY);
}

// round 2
// speedup vs baseline: 2.8688x; 2.8688x over previous
#include <cuda_runtime.h>
#include <cstdint>

// ----------------------------------------------------------------------------
// Attention_53944789237811  (round 2: tf32 tensor-core GEMMs)
//   keys    = LayerNorm(Y @ K) * g1 + b1          [B,S,H]
//   queries = LayerNorm(X @ Q) * g2 + b2          [B,S,H]
//   alpha   = softmax(queries @ keys^T / H)       [B,S,S]
//   out     = alpha @ Y                           [B,S,F]
// B=8, S=2048, F=H=1024.
// ----------------------------------------------------------------------------

#define BM 128
#define BN 128
#define BK 32
#define LDK 36    // row stride (words) for [rows][K] smem tiles (144B, 16B-aligned)
#define LDN 132   // row stride (words) for [K][N] smem tile   (528B, 16B-aligned)

// Scratch: __device__ globals (no cudaMalloc allowed).
__device__ float g_keys   [8ull * 2048 * 1024];   //  64 MB
__device__ float g_queries[8ull * 2048 * 1024];   //  64 MB
__device__ float g_alpha  [8ull * 2048 * 2048];   // 128 MB

__device__ __forceinline__ uint32_t f2tf32(float x) {
    uint32_t r;
    asm("cvt.rna.tf32.f32 %0, %1;" : "=r"(r) : "f"(x));
    return r;
}

__device__ __forceinline__ void mma_tf32(float* c, const uint32_t* a, const uint32_t* b) {
    asm volatile(
        "mma.sync.aligned.m16n8k8.row.col.f32.tf32.tf32.f32 "
        "{%0,%1,%2,%3}, {%4,%5,%6,%7}, {%8,%9}, {%0,%1,%2,%3};\n"
        : "+f"(c[0]), "+f"(c[1]), "+f"(c[2]), "+f"(c[3])
        : "r"(a[0]), "r"(a[1]), "r"(a[2]), "r"(a[3]), "r"(b[0]), "r"(b[1]));
}

// ----------------------------------------------------------------------------
// TF32 tensor-core GEMM: C[M,N] = A[M,K] * B
//   TRANS_B=false: B is [K,N] row-major.  TRANS_B=true: B is [N,K] row-major.
// 128x128x32 CTA tile, 256 threads (8 warps), warp tile 32x64 (2x8 m16n8k8).
// M,N multiples of 128; K multiple of 32. blockIdx.z = batch.
// ----------------------------------------------------------------------------
template <bool TRANS_B>
__global__ __launch_bounds__(256) void mma_gemm(
    const float* __restrict__ A, const float* __restrict__ B,
    float* __restrict__ C,
    int M, int N, int Kd,
    long long sA, long long sB, long long sC)
{
    A += (long long)blockIdx.z * sA;
    B += (long long)blockIdx.z * sB;
    C += (long long)blockIdx.z * sC;

    __shared__ uint32_t As[BM * LDK];                                // [m][k]
    __shared__ uint32_t Bs[TRANS_B ? (BN * LDK) : (BK * LDN)];       // [n][k] or [k][n]

    const int tid  = threadIdx.x;
    const int warp = tid >> 5;
    const int lane = tid & 31;
    const int gid  = lane >> 2;   // 0..7
    const int tig  = lane & 3;    // 0..3

    const int warp_m = warp & 3;          // 0..3
    const int warp_n = warp >> 2;         // 0..1
    const int m_base = warp_m * 32;
    const int n_base = warp_n * 64;

    const int row0 = blockIdx.y * BM;
    const int col0 = blockIdx.x * BN;

    // global-load mappings (4 float4 per thread per tile)
    const int a_row = tid >> 3;           // 0..31 (advances by 32 per chunk)
    const int a_kc  = (tid & 7) * 4;      // 0..28
    const int bnn_kr = tid >> 6;          // 0..3  (advances by 4) [K,N] tile
    const int bnn_nc = (tid & 63) * 4 >= 256 ? 0 : (tid & 63) * 4;  // placeholder, fixed below

    float acc[2][8][4];
#pragma unroll
    for (int i = 0; i < 2; i++)
#pragma unroll
        for (int j = 0; j < 8; j++)
#pragma unroll
            for (int l = 0; l < 4; l++) acc[i][j][l] = 0.f;

    float4 Ar[4], Br[4];

    // ---- prologue: load tile k0=0 into registers ----
    {
#pragma unroll
        for (int i = 0; i < 4; i++) {
            int r = a_row + i * 32;
            Ar[i] = *(const float4*)(A + (long long)(row0 + r) * Kd + a_kc);
        }
        if (TRANS_B) {
#pragma unroll
            for (int i = 0; i < 4; i++) {
                int r = a_row + i * 32;
                Br[i] = *(const float4*)(B + (long long)(col0 + r) * Kd + a_kc);
            }
        } else {
            int kr = tid >> 5;            // 0..7
            int nc = (tid & 31) * 4;      // 0..124
#pragma unroll
            for (int i = 0; i < 4; i++)
                Br[i] = *(const float4*)(B + (long long)(kr + i * 8) * N + col0 + nc);
        }
    }

    for (int k0 = 0; k0 < Kd; k0 += BK) {
        // ---- store staged tile to smem (with tf32 rounding) ----
#pragma unroll
        for (int i = 0; i < 4; i++) {
            int r = a_row + i * 32;
            uint4 v = make_uint4(f2tf32(Ar[i].x), f2tf32(Ar[i].y),
                                 f2tf32(Ar[i].z), f2tf32(Ar[i].w));
            *(uint4*)&As[r * LDK + a_kc] = v;
        }
        if (TRANS_B) {
#pragma unroll
            for (int i = 0; i < 4; i++) {
                int r = a_row + i * 32;
                uint4 v = make_uint4(f2tf32(Br[i].x), f2tf32(Br[i].y),
                                     f2tf32(Br[i].z), f2tf32(Br[i].w));
                *(uint4*)&Bs[r * LDK + a_kc] = v;
            }
        } else {
            int kr = tid >> 5;
            int nc = (tid & 31) * 4;
#pragma unroll
            for (int i = 0; i < 4; i++) {
                uint4 v = make_uint4(f2tf32(Br[i].x), f2tf32(Br[i].y),
                                     f2tf32(Br[i].z), f2tf32(Br[i].w));
                *(uint4*)&Bs[(kr + i * 8) * LDN + nc] = v;
            }
        }
        __syncthreads();

        // ---- prefetch next tile into registers (overlaps with MMA below) ----
        if (k0 + BK < Kd) {
            int kn = k0 + BK;
#pragma unroll
            for (int i = 0; i < 4; i++) {
                int r = a_row + i * 32;
                Ar[i] = *(const float4*)(A + (long long)(row0 + r) * Kd + kn + a_kc);
            }
            if (TRANS_B) {
#pragma unroll
                for (int i = 0; i < 4; i++) {
                    int r = a_row + i * 32;
                    Br[i] = *(const float4*)(B + (long long)(col0 + r) * Kd + kn + a_kc);
                }
            } else {
                int kr = tid >> 5;
                int nc = (tid & 31) * 4;
#pragma unroll
                for (int i = 0; i < 4; i++)
                    Br[i] = *(const float4*)(B + (long long)(kn + kr + i * 8) * N + col0 + nc);
            }
        }

        // ---- compute: 4 k-steps of m16n8k8 ----
#pragma unroll
        for (int kk = 0; kk < BK; kk += 8) {
            uint32_t a[2][4], b[8][2];
#pragma unroll
            for (int mt = 0; mt < 2; mt++) {
                int m = m_base + mt * 16 + gid;
                a[mt][0] = As[m * LDK + kk + tig];
                a[mt][1] = As[(m + 8) * LDK + kk + tig];
                a[mt][2] = As[m * LDK + kk + tig + 4];
                a[mt][3] = As[(m + 8) * LDK + kk + tig + 4];
            }
#pragma unroll
            for (int nt = 0; nt < 8; nt++) {
                int n = n_base + nt * 8 + gid;
                if (TRANS_B) {
                    b[nt][0] = Bs[n * LDK + kk + tig];
                    b[nt][1] = Bs[n * LDK + kk + tig + 4];
                } else {
                    b[nt][0] = Bs[(kk + tig) * LDN + n];
                    b[nt][1] = Bs[(kk + tig + 4) * LDN + n];
                }
            }
#pragma unroll
            for (int mt = 0; mt < 2; mt++)
#pragma unroll
                for (int nt = 0; nt < 8; nt++)
                    mma_tf32(acc[mt][nt], a[mt], b[nt]);
        }
        __syncthreads();
    }

    // ---- epilogue ----
#pragma unroll
    for (int mt = 0; mt < 2; mt++) {
#pragma unroll
        for (int nt = 0; nt < 8; nt++) {
            int r = row0 + m_base + mt * 16 + gid;
            int c = col0 + n_base + nt * 8 + tig * 2;
            *(float2*)(C + (long long)r * N + c) =
                make_float2(acc[mt][nt][0], acc[mt][nt][1]);
            *(float2*)(C + (long long)(r + 8) * N + c) =
                make_float2(acc[mt][nt][2], acc[mt][nt][3]);
        }
    }
}

// ----------------------------------------------------------------------------
// LayerNorm in-place over rows of length 1024. One block (256 thr) per row.
// ----------------------------------------------------------------------------
__global__ __launch_bounds__(256) void layernorm_kernel(
    float* __restrict__ data,
    const float* __restrict__ gamma, const float* __restrict__ beta)
{
    const int H = 1024;
    float* row = data + (long long)blockIdx.x * H;
    const int t = threadIdx.x;
    const int lane = t & 31, wid = t >> 5;

    float v[4];
    float s = 0.f, q = 0.f;
#pragma unroll
    for (int i = 0; i < 4; i++) {
        v[i] = row[t + i * 256];
        s += v[i];
        q += v[i] * v[i];
    }
#pragma unroll
    for (int o = 16; o > 0; o >>= 1) {
        s += __shfl_xor_sync(0xffffffffu, s, o);
        q += __shfl_xor_sync(0xffffffffu, q, o);
    }
    __shared__ float ss[8], sq[8];
    if (lane == 0) { ss[wid] = s; sq[wid] = q; }
    __syncthreads();
    if (wid == 0) {
        float s2 = (lane < 8) ? ss[lane] : 0.f;
        float q2 = (lane < 8) ? sq[lane] : 0.f;
#pragma unroll
        for (int o = 4; o > 0; o >>= 1) {
            s2 += __shfl_xor_sync(0xffffffffu, s2, o);
            q2 += __shfl_xor_sync(0xffffffffu, q2, o);
        }
        if (lane == 0) { ss[0] = s2; sq[0] = q2; }
    }
    __syncthreads();
    const float mu  = ss[0] * (1.f / 1024.f);
    const float var = sq[0] * (1.f / 1024.f) - mu * mu;
    const float inv = rsqrtf(var + 1e-5f);
#pragma unroll
    for (int i = 0; i < 4; i++) {
        const int c = t + i * 256;
        row[c] = (v[i] - mu) * inv * gamma[c] + beta[c];
    }
}

// ----------------------------------------------------------------------------
// Softmax in-place over rows of length 2048, pre-scale 1/1024.
// ----------------------------------------------------------------------------
__global__ __launch_bounds__(256) void softmax_kernel(float* __restrict__ alpha)
{
    const int S = 2048;
    float* row = alpha + (long long)blockIdx.x * S;
    const int t = threadIdx.x;
    const int lane = t & 31, wid = t >> 5;
    const float scale = 1.0f / 1024.0f;

    __shared__ float sbuf[8];

    float v[8];
    float mx = -1e30f;
#pragma unroll
    for (int i = 0; i < 8; i++) {
        v[i] = row[t + i * 256] * scale;
        mx = fmaxf(mx, v[i]);
    }
#pragma unroll
    for (int o = 16; o > 0; o >>= 1)
        mx = fmaxf(mx, __shfl_xor_sync(0xffffffffu, mx, o));
    if (lane == 0) sbuf[wid] = mx;
    __syncthreads();
    if (wid == 0) {
        float m2 = (lane < 8) ? sbuf[lane] : -1e30f;
#pragma unroll
        for (int o = 4; o > 0; o >>= 1)
            m2 = fmaxf(m2, __shfl_xor_sync(0xffffffffu, m2, o));
        if (lane == 0) sbuf[0] = m2;
    }
    __syncthreads();
    mx = sbuf[0];
    __syncthreads();

    float s = 0.f;
#pragma unroll
    for (int i = 0; i < 8; i++) {
        v[i] = expf(v[i] - mx);
        s += v[i];
    }
#pragma unroll
    for (int o = 16; o > 0; o >>= 1)
        s += __shfl_xor_sync(0xffffffffu, s, o);
    if (lane == 0) sbuf[wid] = s;
    __syncthreads();
    if (wid == 0) {
        float s2 = (lane < 8) ? sbuf[lane] : 0.f;
#pragma unroll
        for (int o = 4; o > 0; o >>= 1)
            s2 += __shfl_xor_sync(0xffffffffu, s2, o);
        if (lane == 0) sbuf[0] = s2;
    }
    __syncthreads();
    const float inv = 1.f / sbuf[0];
#pragma unroll
    for (int i = 0; i < 8; i++)
        row[t + i * 256] = v[i] * inv;
}

// ----------------------------------------------------------------------------
// kernel_launch: inputs in metadata order: X, Y, K, Q, g1, b1, g2, b2
// ----------------------------------------------------------------------------
extern "C" void kernel_launch(void* const* d_in, const int* in_sizes, int n_in,
                              void* d_out, int out_size)
{
    const float* X  = (const float*)d_in[0];
    const float* Y  = (const float*)d_in[1];
    const float* K  = (const float*)d_in[2];
    const float* Q  = (const float*)d_in[3];
    const float* g1 = (const float*)d_in[4];
    const float* b1 = (const float*)d_in[5];
    const float* g2 = (const float*)d_in[6];
    const float* b2 = (const float*)d_in[7];
    float* out = (float*)d_out;

    float *keys, *queries, *alpha;
    cudaGetSymbolAddress((void**)&keys,    g_keys);
    cudaGetSymbolAddress((void**)&queries, g_queries);
    cudaGetSymbolAddress((void**)&alpha,   g_alpha);

    const int B = 8, S = 2048, F = 1024, H = 1024;
    const long long sQK = (long long)S * H;
    const long long sAL = (long long)S * S;
    const long long sY  = (long long)S * F;

    dim3 blk(256);

    // 1) projections: keys_raw = Y@K, queries_raw = X@Q   ([16384,1024]x[1024,1024])
    mma_gemm<false><<<dim3(H / BN, (B * S) / BM, 1), blk>>>(
        Y, K, keys, B * S, H, F, 0, 0, 0);
    mma_gemm<false><<<dim3(H / BN, (B * S) / BM, 1), blk>>>(
        X, Q, queries, B * S, H, F, 0, 0, 0);

    // 2) layernorms (in-place)
    layernorm_kernel<<<B * S, 256>>>(keys, g1, b1);
    layernorm_kernel<<<B * S, 256>>>(queries, g2, b2);

    // 3) logits: alpha[b] = queries[b] @ keys[b]^T   (NT, per batch)
    mma_gemm<true><<<dim3(S / BN, S / BM, B), blk>>>(
        queries, keys, alpha, S, S, H, sQK, sQK, sAL);

    // 4) softmax rows (scale 1/H applied inside)
    softmax_kernel<<<B * S, 256>>>(alpha);

    // 5) out[b] = alpha[b] @ Y[b]   (NN, per batch)
    mma_gemm<false><<<dim3(F / BN, S / BM, B), blk>>>(
        alpha, Y, out, S, F, S, sAL, sY, sY);
}

// round 4
// speedup vs baseline: 4.1136x; 1.4339x over previous
#include <cuda_runtime.h>
#include <cstdint>

// ----------------------------------------------------------------------------
// Attention_53944789237811  (round 4: mma.sync tf32 + ldmatrix + cp.async)
//   keys    = LayerNorm(Y @ K) * g1 + b1          [B,S,H]
//   queries = LayerNorm(X @ Q) * g2 + b2          [B,S,H]
//   alpha   = softmax(queries @ keys^T / H)       [B,S,S]
//   out     = alpha @ Y                           [B,S,F]
// B=8, S=2048, F=H=1024.
// Harness compiles at compute_103 (non-'a'): tcgen05 unavailable. This round
// saturates the legacy HMMA pipe: ldmatrix fragment loads + 3-stage cp.async.
// ----------------------------------------------------------------------------

// ---------------- scratch (device globals; no cudaMalloc allowed) ------------
__device__ float g_keys   [8ull * 2048 * 1024];   //  64 MB
__device__ float g_queries[8ull * 2048 * 1024];   //  64 MB
__device__ float g_alpha  [8ull * 2048 * 2048];   // 128 MB
__device__ float g_xr     [8ull * 2048 * 1024];   //  64 MB (X rounded to tf32)
__device__ float g_yr     [8ull * 2048 * 1024];   //  64 MB (Y rounded to tf32)
__device__ float g_kt     [1024ull * 1024];       //   4 MB (K^T rounded)
__device__ float g_qt     [1024ull * 1024];       //   4 MB (Q^T rounded)
__device__ float g_yt     [8ull * 1024 * 2048];   //  64 MB (Y^T rounded)

// ---------------- helpers ------------------------------------------------------
__device__ __forceinline__ uint32_t f2tf32(float x) {
    uint32_t r;
    asm("cvt.rna.tf32.f32 %0, %1;" : "=r"(r) : "f"(x));
    return r;
}
__device__ __forceinline__ float rnd_tf32(float x) {
    return __uint_as_float(f2tf32(x));
}
__device__ __forceinline__ uint32_t smem_u32(const void* p) {
    uint32_t a;
    asm("{ .reg .u64 t; cvta.to.shared.u64 t, %1; cvt.u32.u64 %0, t; }"
        : "=r"(a) : "l"(p));
    return a;
}

__device__ __forceinline__ void mma_tf32(float* c, const uint32_t* a, const uint32_t* b) {
    asm volatile(
        "mma.sync.aligned.m16n8k8.row.col.f32.tf32.tf32.f32 "
        "{%0,%1,%2,%3}, {%4,%5,%6,%7}, {%8,%9}, {%0,%1,%2,%3};\n"
        : "+f"(c[0]), "+f"(c[1]), "+f"(c[2]), "+f"(c[3])
        : "r"(a[0]), "r"(a[1]), "r"(a[2]), "r"(a[3]), "r"(b[0]), "r"(b[1]));
}

__device__ __forceinline__ void ldsm4(uint32_t* r, uint32_t addr) {
    asm volatile("ldmatrix.sync.aligned.m8n8.x4.shared.b16 {%0,%1,%2,%3}, [%4];"
                 : "=r"(r[0]), "=r"(r[1]), "=r"(r[2]), "=r"(r[3]) : "r"(addr));
}

__device__ __forceinline__ void cp16(uint32_t dst, const float* src) {
    asm volatile("cp.async.cg.shared.global [%0], [%1], 16;"
                 :: "r"(dst), "l"(src) : "memory");
}
#define CP_COMMIT() asm volatile("cp.async.commit_group;" ::: "memory")

#define SWZ(o) ((o) ^ ((((uint32_t)(o)) >> 3) & 0x70u))

// ---------------- tf32 tensor GEMM ---------------------------------------------
// C[M,N] = A[M,K] * B[N,K]^T.  A,B row-major, K contiguous, pre-rounded tf32.
// CTA tile 128x128, BK=32 (128B rows -> SW128 swizzle), 3-stage cp.async,
// 256 threads (8 warps, warp tile 32x64), ldmatrix.x4 fragment loads.
#define TILEB  16384          // one operand tile (128 rows x 128B)
#define STAGEB 32768          // A+B per stage
#define GSMEM  (3 * STAGEB)   // 96 KB

__device__ __forceinline__ void load_stage(
    const float* A, const float* B, int Kd, int row0, int col0, int kk,
    uint32_t abuf, uint32_t bbuf, int tid)
{
#pragma unroll
    for (int i = 0; i < 4; i++) {
        int ch = tid + i * 256;            // 1024 chunks of 16B
        int r = ch >> 3, c = ch & 7;
        cp16(abuf + SWZ(r * 128 + c * 16),
             A + (long long)(row0 + r) * Kd + kk + c * 4);
    }
#pragma unroll
    for (int i = 0; i < 4; i++) {
        int ch = tid + i * 256;
        int r = ch >> 3, c = ch & 7;
        cp16(bbuf + SWZ(r * 128 + c * 16),
             B + (long long)(col0 + r) * Kd + kk + c * 4);
    }
    CP_COMMIT();
}

__global__ __launch_bounds__(256, 2)
void gemm_mma(const float* __restrict__ A, const float* __restrict__ B,
              float* __restrict__ C, int M, int N, int Kd,
              long long sA, long long sB, long long sC)
{
    extern __shared__ __align__(1024) char smem[];
    A += (long long)blockIdx.z * sA;
    B += (long long)blockIdx.z * sB;
    C += (long long)blockIdx.z * sC;

    const uint32_t sbase = smem_u32(smem);
    const int tid  = threadIdx.x;
    const int warp = tid >> 5;
    const int lane = tid & 31;
    const int gid  = lane >> 2;
    const int tig  = lane & 3;
    const int warp_m = warp & 3;   // 4 warps over M (32 rows each)
    const int warp_n = warp >> 2;  // 2 warps over N (64 cols each)
    const int row0 = blockIdx.y * 128;
    const int col0 = blockIdx.x * 128;

    // lane-constant ldmatrix address components
    const int l7 = lane & 7;
    uint32_t aoff[2], axm[2];
#pragma unroll
    for (int mt = 0; mt < 2; mt++) {
        int row = warp_m * 32 + mt * 16 + l7 + ((lane >> 3) & 1) * 8;
        aoff[mt] = (uint32_t)row * 128;
        axm[mt]  = (uint32_t)(row & 7) * 16;
    }
    const uint32_t aq = (uint32_t)(lane >> 4) * 16;
    uint32_t boff[4], bxm[4];
#pragma unroll
    for (int p = 0; p < 4; p++) {
        int row = warp_n * 64 + p * 16 + ((lane >> 4) & 1) * 8 + l7;
        boff[p] = (uint32_t)row * 128;
        bxm[p]  = (uint32_t)(row & 7) * 16;
    }
    const uint32_t bq = (uint32_t)((lane >> 3) & 1) * 16;

    float acc[2][8][4];
#pragma unroll
    for (int i = 0; i < 2; i++)
#pragma unroll
        for (int j = 0; j < 8; j++)
#pragma unroll
            for (int l = 0; l < 4; l++) acc[i][j][l] = 0.f;

    const int nst = Kd / 32;

    // prologue: stages 0,1
    load_stage(A, B, Kd, row0, col0, 0,
               sbase, sbase + TILEB, tid);
    load_stage(A, B, Kd, row0, col0, 32,
               sbase + STAGEB, sbase + STAGEB + TILEB, tid);

    for (int s = 0; s < nst; s++) {
        if (s + 1 < nst)
            asm volatile("cp.async.wait_group 1;" ::: "memory");
        else
            asm volatile("cp.async.wait_group 0;" ::: "memory");
        __syncthreads();

        int bufi = s % 3;
        const uint32_t abuf = sbase + bufi * STAGEB;
        const uint32_t bbuf = abuf + TILEB;

#pragma unroll
        for (int kg = 0; kg < 4; kg++) {
            uint32_t a[2][4], b[4][4];
#pragma unroll
            for (int mt = 0; mt < 2; mt++)
                ldsm4(a[mt], abuf + aoff[mt] + (((uint32_t)kg * 32 + aq) ^ axm[mt]));
#pragma unroll
            for (int p = 0; p < 4; p++)
                ldsm4(b[p], bbuf + boff[p] + (((uint32_t)kg * 32 + bq) ^ bxm[p]));
#pragma unroll
            for (int mt = 0; mt < 2; mt++)
#pragma unroll
                for (int nt = 0; nt < 8; nt++)
                    mma_tf32(acc[mt][nt], a[mt], &b[nt >> 1][(nt & 1) * 2]);
        }

        if (s + 2 < nst) {
            int t = s + 2;
            const uint32_t nabuf = sbase + (t % 3) * STAGEB;
            load_stage(A, B, Kd, row0, col0, t * 32,
                       nabuf, nabuf + TILEB, tid);
        }
    }

    // epilogue
#pragma unroll
    for (int mt = 0; mt < 2; mt++) {
#pragma unroll
        for (int nt = 0; nt < 8; nt++) {
            int r = row0 + warp_m * 32 + mt * 16 + gid;
            int c = col0 + warp_n * 64 + nt * 8 + tig * 2;
            *(float2*)(C + (long long)r * N + c) =
                make_float2(acc[mt][nt][0], acc[mt][nt][1]);
            *(float2*)(C + (long long)(r + 8) * N + c) =
                make_float2(acc[mt][nt][2], acc[mt][nt][3]);
        }
    }
}

// ---------------- pre-pass kernels ---------------------------------------------
__global__ __launch_bounds__(256) void round_copy(const float4* __restrict__ in,
                                                  float4* __restrict__ out, int n4)
{
    int i = blockIdx.x * 256 + threadIdx.x;
    int stride = gridDim.x * 256;
    for (; i < n4; i += stride) {
        float4 v = in[i];
        v.x = rnd_tf32(v.x); v.y = rnd_tf32(v.y);
        v.z = rnd_tf32(v.z); v.w = rnd_tf32(v.w);
        out[i] = v;
    }
}

// out[c][r] = round(in[r][c]); in [R,C] row-major, out [C,R]; batch = blockIdx.z
__global__ __launch_bounds__(256) void trans_round(
    const float* __restrict__ in, float* __restrict__ out,
    int R, int C, long long sIn, long long sOut)
{
    in  += (long long)blockIdx.z * sIn;
    out += (long long)blockIdx.z * sOut;
    __shared__ float t[32][33];
    const int r0 = blockIdx.y * 32, c0 = blockIdx.x * 32;
    const int tx = threadIdx.x & 31, ty = threadIdx.x >> 5;  // 32 x 8
#pragma unroll
    for (int i = 0; i < 32; i += 8)
        t[ty + i][tx] = rnd_tf32(in[(long long)(r0 + ty + i) * C + c0 + tx]);
    __syncthreads();
#pragma unroll
    for (int i = 0; i < 32; i += 8)
        out[(long long)(c0 + ty + i) * R + r0 + tx] = t[tx][ty + i];
}

// ---------------- layernorm (rounds output to tf32) -----------------------------
__global__ __launch_bounds__(256) void layernorm_kernel(
    float* __restrict__ data,
    const float* __restrict__ gamma, const float* __restrict__ beta)
{
    const int H = 1024;
    float* row = data + (long long)blockIdx.x * H;
    const int t = threadIdx.x;
    const int lane = t & 31, wid = t >> 5;

    float v[4];
    float s = 0.f, q = 0.f;
#pragma unroll
    for (int i = 0; i < 4; i++) {
        v[i] = row[t + i * 256];
        s += v[i];
        q += v[i] * v[i];
    }
#pragma unroll
    for (int o = 16; o > 0; o >>= 1) {
        s += __shfl_xor_sync(0xffffffffu, s, o);
        q += __shfl_xor_sync(0xffffffffu, q, o);
    }
    __shared__ float ss[8], sq[8];
    if (lane == 0) { ss[wid] = s; sq[wid] = q; }
    __syncthreads();
    if (wid == 0) {
        float s2 = (lane < 8) ? ss[lane] : 0.f;
        float q2 = (lane < 8) ? sq[lane] : 0.f;
#pragma unroll
        for (int o = 4; o > 0; o >>= 1) {
            s2 += __shfl_xor_sync(0xffffffffu, s2, o);
            q2 += __shfl_xor_sync(0xffffffffu, q2, o);
        }
        if (lane == 0) { ss[0] = s2; sq[0] = q2; }
    }
    __syncthreads();
    const float mu  = ss[0] * (1.f / 1024.f);
    const float var = sq[0] * (1.f / 1024.f) - mu * mu;
    const float inv = rsqrtf(var + 1e-5f);
#pragma unroll
    for (int i = 0; i < 4; i++) {
        const int c = t + i * 256;
        row[c] = rnd_tf32((v[i] - mu) * inv * gamma[c] + beta[c]);
    }
}

// ---------------- softmax (scale 1/1024, rounds output to tf32) -----------------
__global__ __launch_bounds__(256) void softmax_kernel(float* __restrict__ alpha)
{
    const int S = 2048;
    float* row = alpha + (long long)blockIdx.x * S;
    const int t = threadIdx.x;
    const int lane = t & 31, wid = t >> 5;
    const float scale = 1.0f / 1024.0f;

    __shared__ float sbuf[8];

    float v[8];
    float mx = -1e30f;
#pragma unroll
    for (int i = 0; i < 8; i++) {
        v[i] = row[t + i * 256] * scale;
        mx = fmaxf(mx, v[i]);
    }
#pragma unroll
    for (int o = 16; o > 0; o >>= 1)
        mx = fmaxf(mx, __shfl_xor_sync(0xffffffffu, mx, o));
    if (lane == 0) sbuf[wid] = mx;
    __syncthreads();
    if (wid == 0) {
        float m2 = (lane < 8) ? sbuf[lane] : -1e30f;
#pragma unroll
        for (int o = 4; o > 0; o >>= 1)
            m2 = fmaxf(m2, __shfl_xor_sync(0xffffffffu, m2, o));
        if (lane == 0) sbuf[0] = m2;
    }
    __syncthreads();
    mx = sbuf[0];
    __syncthreads();

    float s = 0.f;
#pragma unroll
    for (int i = 0; i < 8; i++) {
        v[i] = expf(v[i] - mx);
        s += v[i];
    }
#pragma unroll
    for (int o = 16; o > 0; o >>= 1)
        s += __shfl_xor_sync(0xffffffffu, s, o);
    if (lane == 0) sbuf[wid] = s;
    __syncthreads();
    if (wid == 0) {
        float s2 = (lane < 8) ? sbuf[lane] : 0.f;
#pragma unroll
        for (int o = 4; o > 0; o >>= 1)
            s2 += __shfl_xor_sync(0xffffffffu, s2, o);
        if (lane == 0) sbuf[0] = s2;
    }
    __syncthreads();
    const float inv = 1.f / sbuf[0];
#pragma unroll
    for (int i = 0; i < 8; i++)
        row[t + i * 256] = rnd_tf32(v[i] * inv);
}

// ---------------- kernel_launch --------------------------------------------------
extern "C" void kernel_launch(void* const* d_in, const int* in_sizes, int n_in,
                              void* d_out, int out_size)
{
    const float* X  = (const float*)d_in[0];
    const float* Y  = (const float*)d_in[1];
    const float* K  = (const float*)d_in[2];
    const float* Q  = (const float*)d_in[3];
    const float* g1 = (const float*)d_in[4];
    const float* b1 = (const float*)d_in[5];
    const float* g2 = (const float*)d_in[6];
    const float* b2 = (const float*)d_in[7];
    float* out = (float*)d_out;

    float *keys, *queries, *alpha, *xr, *yr, *kt, *qt, *yt;
    cudaGetSymbolAddress((void**)&keys,    g_keys);
    cudaGetSymbolAddress((void**)&queries, g_queries);
    cudaGetSymbolAddress((void**)&alpha,   g_alpha);
    cudaGetSymbolAddress((void**)&xr,      g_xr);
    cudaGetSymbolAddress((void**)&yr,      g_yr);
    cudaGetSymbolAddress((void**)&kt,      g_kt);
    cudaGetSymbolAddress((void**)&qt,      g_qt);
    cudaGetSymbolAddress((void**)&yt,      g_yt);

    cudaFuncSetAttribute(gemm_mma, cudaFuncAttributeMaxDynamicSharedMemorySize, GSMEM);

    const int B = 8, S = 2048, F = 1024, H = 1024;
    const long long nXY = (long long)B * S * F;
    const long long sQK = (long long)S * H;
    const long long sAL = (long long)S * S;
    const long long sY  = (long long)S * F;
    const long long sYT = (long long)F * S;

    // 1) tf32-round inputs; build rounded transposes K^T, Q^T, Y^T
    round_copy<<<2048, 256>>>((const float4*)X, (float4*)xr, (int)(nXY / 4));
    round_copy<<<2048, 256>>>((const float4*)Y, (float4*)yr, (int)(nXY / 4));
    trans_round<<<dim3(H / 32, F / 32, 1), 256>>>(K, kt, F, H, 0, 0);    // kt[H,F]
    trans_round<<<dim3(H / 32, F / 32, 1), 256>>>(Q, qt, F, H, 0, 0);    // qt[H,F]
    trans_round<<<dim3(F / 32, S / 32, B), 256>>>(Y, yt, S, F, sY, sYT); // yt[F,S]

    // 2) projections: keys_raw = yr @ kt^T, queries_raw = xr @ qt^T
    gemm_mma<<<dim3(H / 128, (B * S) / 128, 1), 256, GSMEM>>>(
        yr, kt, keys, B * S, H, F, 0, 0, 0);
    gemm_mma<<<dim3(H / 128, (B * S) / 128, 1), 256, GSMEM>>>(
        xr, qt, queries, B * S, H, F, 0, 0, 0);

    // 3) layernorms (in-place, outputs tf32-rounded)
    layernorm_kernel<<<B * S, 256>>>(keys, g1, b1);
    layernorm_kernel<<<B * S, 256>>>(queries, g2, b2);

    // 4) logits: alpha[b] = queries[b] @ keys[b]^T
    gemm_mma<<<dim3(S / 128, S / 128, B), 256, GSMEM>>>(
        queries, keys, alpha, S, S, H, sQK, sQK, sAL);

    // 5) softmax rows (applies 1/H scale, rounds output)
    softmax_kernel<<<B * S, 256>>>(alpha);

    // 6) out[b] = alpha[b] @ yt[b]^T
    gemm_mma<<<dim3(F / 128, S / 128, B), 256, GSMEM>>>(
        alpha, yt, out, S, F, S, sAL, sYT, sY);
}

// round 5
// speedup vs baseline: 6.9832x; 1.6976x over previous
#include <cuda_runtime.h>
#include <cuda_fp16.h>
#include <cstdint>

// ----------------------------------------------------------------------------
// Attention_53944789237811  (round 5: fp16 mma.m16n8k16, f32 accumulate)
//   keys    = LayerNorm(Y @ K) * g1 + b1          [B,S,H]
//   queries = LayerNorm(X @ Q) * g2 + b2          [B,S,H]
//   alpha   = softmax(queries @ keys^T / H)       [B,S,S]
//   out     = alpha @ Y                           [B,S,F]
// B=8, S=2048, F=H=1024.
// fp16 operands (10-bit mantissa == tf32) with f32 accumulation: same accuracy
// as the tf32 path, 2x tensor throughput, half the operand traffic.
// ----------------------------------------------------------------------------

// ---------------- scratch (device globals; no cudaMalloc allowed) ------------
__device__ float  g_keys_f   [8ull * 2048 * 1024];  //  64 MB (proj raw f32)
__device__ float  g_queries_f[8ull * 2048 * 1024];  //  64 MB
__device__ float  g_alpha_f  [8ull * 2048 * 2048];  // 128 MB (logits f32)
__device__ __half g_xh   [8ull * 2048 * 1024];      //  32 MB
__device__ __half g_yh   [8ull * 2048 * 1024];      //  32 MB
__device__ __half g_kth  [1024ull * 1024];          //   2 MB (K^T)
__device__ __half g_qth  [1024ull * 1024];          //   2 MB (Q^T)
__device__ __half g_yth  [8ull * 1024 * 2048];      //  32 MB (Y^T)
__device__ __half g_keysh   [8ull * 2048 * 1024];   //  32 MB (LN'd keys)
__device__ __half g_queriesh[8ull * 2048 * 1024];   //  32 MB
__device__ __half g_alphah  [8ull * 2048 * 2048];   //  64 MB (softmaxed)

// ---------------- helpers ------------------------------------------------------
__device__ __forceinline__ uint32_t smem_u32(const void* p) {
    uint32_t a;
    asm("{ .reg .u64 t; cvta.to.shared.u64 t, %1; cvt.u32.u64 %0, t; }"
        : "=r"(a) : "l"(p));
    return a;
}

__device__ __forceinline__ void mma_fp16(float* c, const uint32_t* a, const uint32_t* b) {
    asm volatile(
        "mma.sync.aligned.m16n8k16.row.col.f32.f16.f16.f32 "
        "{%0,%1,%2,%3}, {%4,%5,%6,%7}, {%8,%9}, {%0,%1,%2,%3};\n"
        : "+f"(c[0]), "+f"(c[1]), "+f"(c[2]), "+f"(c[3])
        : "r"(a[0]), "r"(a[1]), "r"(a[2]), "r"(a[3]), "r"(b[0]), "r"(b[1]));
}

__device__ __forceinline__ void ldsm4(uint32_t* r, uint32_t addr) {
    asm volatile("ldmatrix.sync.aligned.m8n8.x4.shared.b16 {%0,%1,%2,%3}, [%4];"
                 : "=r"(r[0]), "=r"(r[1]), "=r"(r[2]), "=r"(r[3]) : "r"(addr));
}

__device__ __forceinline__ void cp16(uint32_t dst, const void* src) {
    asm volatile("cp.async.cg.shared.global [%0], [%1], 16;"
                 :: "r"(dst), "l"(src) : "memory");
}
#define CP_COMMIT() asm volatile("cp.async.commit_group;" ::: "memory")

#define SWZ(o) ((o) ^ ((((uint32_t)(o)) >> 3) & 0x70u))

// ---------------- fp16 tensor GEMM ---------------------------------------------
// C[M,N] = A[M,K] * B[N,K]^T.  A,B fp16 row-major (K contiguous). C f32.
// CTA tile 128x128, BK=64 (128B rows -> SW128), 3-stage cp.async,
// 256 threads (8 warps, warp tile 32x64), ldmatrix.x4 fragment loads.
#define TILEB  16384          // 128 rows x 128B
#define STAGEB 32768
#define GSMEM  (3 * STAGEB)   // 96 KB

__device__ __forceinline__ void load_stage(
    const __half* A, const __half* B, int Kd, int row0, int col0, int kk,
    uint32_t abuf, uint32_t bbuf, int tid)
{
#pragma unroll
    for (int i = 0; i < 4; i++) {
        int ch = tid + i * 256;            // 1024 chunks of 16B
        int r = ch >> 3, c = ch & 7;
        cp16(abuf + SWZ(r * 128 + c * 16),
             A + (long long)(row0 + r) * Kd + kk + c * 8);
    }
#pragma unroll
    for (int i = 0; i < 4; i++) {
        int ch = tid + i * 256;
        int r = ch >> 3, c = ch & 7;
        cp16(bbuf + SWZ(r * 128 + c * 16),
             B + (long long)(col0 + r) * Kd + kk + c * 8);
    }
    CP_COMMIT();
}

__global__ __launch_bounds__(256, 2)
void gemm_h(const __half* __restrict__ A, const __half* __restrict__ B,
            float* __restrict__ C, int M, int N, int Kd,
            long long sA, long long sB, long long sC)
{
    extern __shared__ __align__(1024) char smem[];
    A += (long long)blockIdx.z * sA;
    B += (long long)blockIdx.z * sB;
    C += (long long)blockIdx.z * sC;

    const uint32_t sbase = smem_u32(smem);
    const int tid  = threadIdx.x;
    const int warp = tid >> 5;
    const int lane = tid & 31;
    const int gid  = lane >> 2;
    const int tig  = lane & 3;
    const int warp_m = warp & 3;   // 4 warps over M (32 rows each)
    const int warp_n = warp >> 2;  // 2 warps over N (64 cols each)
    const int row0 = blockIdx.y * 128;
    const int col0 = blockIdx.x * 128;

    // ldmatrix lane-address components.
    // A (m16k16, x4): lanes 0-7 m0-7/k0-7 | 8-15 m8-15/k0-7 | 16-23 m0-7/k8-15 | 24-31 m8-15/k8-15
    const int l7 = lane & 7;
    uint32_t aoff[2], axm[2];
#pragma unroll
    for (int mt = 0; mt < 2; mt++) {
        int row = warp_m * 32 + mt * 16 + ((lane >> 3) & 1) * 8 + l7;
        aoff[mt] = (uint32_t)row * 128;
        axm[mt]  = (uint32_t)(row & 7) * 16;
    }
    const uint32_t aq = (uint32_t)((lane >> 4) & 1) * 16;   // k-halves along bytes
    // B (two n8k16 tiles per x4): lanes 0-7 n0-7/k0-7 | 8-15 n0-7/k8-15 | 16-23 n8-15/k0-7 | 24-31 n8-15/k8-15
    uint32_t boff[4], bxm[4];
#pragma unroll
    for (int p = 0; p < 4; p++) {
        int row = warp_n * 64 + p * 16 + ((lane >> 4) & 1) * 8 + l7;
        boff[p] = (uint32_t)row * 128;
        bxm[p]  = (uint32_t)(row & 7) * 16;
    }
    const uint32_t bq = (uint32_t)((lane >> 3) & 1) * 16;

    float acc[2][8][4];
#pragma unroll
    for (int i = 0; i < 2; i++)
#pragma unroll
        for (int j = 0; j < 8; j++)
#pragma unroll
            for (int l = 0; l < 4; l++) acc[i][j][l] = 0.f;

    const int nst = Kd / 64;

    load_stage(A, B, Kd, row0, col0, 0,  sbase, sbase + TILEB, tid);
    load_stage(A, B, Kd, row0, col0, 64, sbase + STAGEB, sbase + STAGEB + TILEB, tid);

    for (int s = 0; s < nst; s++) {
        if (s + 1 < nst)
            asm volatile("cp.async.wait_group 1;" ::: "memory");
        else
            asm volatile("cp.async.wait_group 0;" ::: "memory");
        __syncthreads();

        const uint32_t abuf = sbase + (s % 3) * STAGEB;
        const uint32_t bbuf = abuf + TILEB;

#pragma unroll
        for (int kg = 0; kg < 4; kg++) {       // 4 x K=16 steps (32B per step)
            uint32_t a[2][4], b[4][4];
#pragma unroll
            for (int mt = 0; mt < 2; mt++)
                ldsm4(a[mt], abuf + aoff[mt] + (((uint32_t)kg * 32 + aq) ^ axm[mt]));
#pragma unroll
            for (int p = 0; p < 4; p++)
                ldsm4(b[p], bbuf + boff[p] + (((uint32_t)kg * 32 + bq) ^ bxm[p]));
#pragma unroll
            for (int mt = 0; mt < 2; mt++)
#pragma unroll
                for (int nt = 0; nt < 8; nt++)
                    mma_fp16(acc[mt][nt], a[mt], &b[nt >> 1][(nt & 1) * 2]);
        }

        if (s + 2 < nst) {
            int t = s + 2;
            const uint32_t nabuf = sbase + (t % 3) * STAGEB;
            load_stage(A, B, Kd, row0, col0, t * 64, nabuf, nabuf + TILEB, tid);
        }
    }

    // epilogue (f32 out)
#pragma unroll
    for (int mt = 0; mt < 2; mt++) {
#pragma unroll
        for (int nt = 0; nt < 8; nt++) {
            int r = row0 + warp_m * 32 + mt * 16 + gid;
            int c = col0 + warp_n * 64 + nt * 8 + tig * 2;
            *(float2*)(C + (long long)r * N + c) =
                make_float2(acc[mt][nt][0], acc[mt][nt][1]);
            *(float2*)(C + (long long)(r + 8) * N + c) =
                make_float2(acc[mt][nt][2], acc[mt][nt][3]);
        }
    }
}

// ---------------- pre-pass kernels ---------------------------------------------
__global__ __launch_bounds__(256) void cvt_half(const float4* __restrict__ in,
                                                __half2* __restrict__ out, int n4)
{
    int i = blockIdx.x * 256 + threadIdx.x;
    int stride = gridDim.x * 256;
    for (; i < n4; i += stride) {
        float4 v = in[i];
        out[i * 2 + 0] = __floats2half2_rn(v.x, v.y);
        out[i * 2 + 1] = __floats2half2_rn(v.z, v.w);
    }
}

// out[c][r] = half(in[r][c]); in [R,C] f32 row-major, out [C,R] half; z = batch
__global__ __launch_bounds__(256) void trans_half(
    const float* __restrict__ in, __half* __restrict__ out,
    int R, int C, long long sIn, long long sOut)
{
    in  += (long long)blockIdx.z * sIn;
    out += (long long)blockIdx.z * sOut;
    __shared__ float t[32][33];
    const int r0 = blockIdx.y * 32, c0 = blockIdx.x * 32;
    const int tx = threadIdx.x & 31, ty = threadIdx.x >> 5;  // 32 x 8
#pragma unroll
    for (int i = 0; i < 32; i += 8)
        t[ty + i][tx] = in[(long long)(r0 + ty + i) * C + c0 + tx];
    __syncthreads();
#pragma unroll
    for (int i = 0; i < 32; i += 8)
        out[(long long)(c0 + ty + i) * R + r0 + tx] = __float2half_rn(t[tx][ty + i]);
}

// ---------------- layernorm: f32 in, half out ------------------------------------
__global__ __launch_bounds__(256) void layernorm_kernel(
    const float* __restrict__ data, __half* __restrict__ outh,
    const float* __restrict__ gamma, const float* __restrict__ beta)
{
    const int H = 1024;
    const float* row = data + (long long)blockIdx.x * H;
    __half* orow = outh + (long long)blockIdx.x * H;
    const int t = threadIdx.x;
    const int lane = t & 31, wid = t >> 5;

    float v[4];
    float s = 0.f, q = 0.f;
#pragma unroll
    for (int i = 0; i < 4; i++) {
        v[i] = row[t + i * 256];
        s += v[i];
        q += v[i] * v[i];
    }
#pragma unroll
    for (int o = 16; o > 0; o >>= 1) {
        s += __shfl_xor_sync(0xffffffffu, s, o);
        q += __shfl_xor_sync(0xffffffffu, q, o);
    }
    __shared__ float ss[8], sq[8];
    if (lane == 0) { ss[wid] = s; sq[wid] = q; }
    __syncthreads();
    if (wid == 0) {
        float s2 = (lane < 8) ? ss[lane] : 0.f;
        float q2 = (lane < 8) ? sq[lane] : 0.f;
#pragma unroll
        for (int o = 4; o > 0; o >>= 1) {
            s2 += __shfl_xor_sync(0xffffffffu, s2, o);
            q2 += __shfl_xor_sync(0xffffffffu, q2, o);
        }
        if (lane == 0) { ss[0] = s2; sq[0] = q2; }
    }
    __syncthreads();
    const float mu  = ss[0] * (1.f / 1024.f);
    const float var = sq[0] * (1.f / 1024.f) - mu * mu;
    const float inv = rsqrtf(var + 1e-5f);
#pragma unroll
    for (int i = 0; i < 4; i++) {
        const int c = t + i * 256;
        orow[c] = __float2half_rn((v[i] - mu) * inv * gamma[c] + beta[c]);
    }
}

// ---------------- softmax: f32 logits in, half out (scale 1/1024) -----------------
__global__ __launch_bounds__(256) void softmax_kernel(
    const float* __restrict__ alpha, __half* __restrict__ outh)
{
    const int S = 2048;
    const float* row = alpha + (long long)blockIdx.x * S;
    __half* orow = outh + (long long)blockIdx.x * S;
    const int t = threadIdx.x;
    const int lane = t & 31, wid = t >> 5;
    const float scale = 1.0f / 1024.0f;

    __shared__ float sbuf[8];

    float v[8];
    float mx = -1e30f;
#pragma unroll
    for (int i = 0; i < 8; i++) {
        v[i] = row[t + i * 256] * scale;
        mx = fmaxf(mx, v[i]);
    }
#pragma unroll
    for (int o = 16; o > 0; o >>= 1)
        mx = fmaxf(mx, __shfl_xor_sync(0xffffffffu, mx, o));
    if (lane == 0) sbuf[wid] = mx;
    __syncthreads();
    if (wid == 0) {
        float m2 = (lane < 8) ? sbuf[lane] : -1e30f;
#pragma unroll
        for (int o = 4; o > 0; o >>= 1)
            m2 = fmaxf(m2, __shfl_xor_sync(0xffffffffu, m2, o));
        if (lane == 0) sbuf[0] = m2;
    }
    __syncthreads();
    mx = sbuf[0];
    __syncthreads();

    float s = 0.f;
#pragma unroll
    for (int i = 0; i < 8; i++) {
        v[i] = expf(v[i] - mx);
        s += v[i];
    }
#pragma unroll
    for (int o = 16; o > 0; o >>= 1)
        s += __shfl_xor_sync(0xffffffffu, s, o);
    if (lane == 0) sbuf[wid] = s;
    __syncthreads();
    if (wid == 0) {
        float s2 = (lane < 8) ? sbuf[lane] : 0.f;
#pragma unroll
        for (int o = 4; o > 0; o >>= 1)
            s2 += __shfl_xor_sync(0xffffffffu, s2, o);
        if (lane == 0) sbuf[0] = s2;
    }
    __syncthreads();
    const float inv = 1.f / sbuf[0];
#pragma unroll
    for (int i = 0; i < 8; i++)
        orow[t + i * 256] = __float2half_rn(v[i] * inv);
}

// ---------------- kernel_launch --------------------------------------------------
extern "C" void kernel_launch(void* const* d_in, const int* in_sizes, int n_in,
                              void* d_out, int out_size)
{
    const float* X  = (const float*)d_in[0];
    const float* Y  = (const float*)d_in[1];
    const float* K  = (const float*)d_in[2];
    const float* Q  = (const float*)d_in[3];
    const float* g1 = (const float*)d_in[4];
    const float* b1 = (const float*)d_in[5];
    const float* g2 = (const float*)d_in[6];
    const float* b2 = (const float*)d_in[7];
    float* out = (float*)d_out;

    float  *keysf, *queriesf, *alphaf;
    __half *xh, *yh, *kth, *qth, *yth, *keysh, *queriesh, *alphah;
    cudaGetSymbolAddress((void**)&keysf,    g_keys_f);
    cudaGetSymbolAddress((void**)&queriesf, g_queries_f);
    cudaGetSymbolAddress((void**)&alphaf,   g_alpha_f);
    cudaGetSymbolAddress((void**)&xh,       g_xh);
    cudaGetSymbolAddress((void**)&yh,       g_yh);
    cudaGetSymbolAddress((void**)&kth,      g_kth);
    cudaGetSymbolAddress((void**)&qth,      g_qth);
    cudaGetSymbolAddress((void**)&yth,      g_yth);
    cudaGetSymbolAddress((void**)&keysh,    g_keysh);
    cudaGetSymbolAddress((void**)&queriesh, g_queriesh);
    cudaGetSymbolAddress((void**)&alphah,   g_alphah);

    cudaFuncSetAttribute(gemm_h, cudaFuncAttributeMaxDynamicSharedMemorySize, GSMEM);

    const int B = 8, S = 2048, F = 1024, H = 1024;
    const long long nXY = (long long)B * S * F;
    const long long sQK = (long long)S * H;
    const long long sAL = (long long)S * S;
    const long long sY  = (long long)S * F;
    const long long sYT = (long long)F * S;

    // 1) fp16 conversions + transposes
    cvt_half<<<2048, 256>>>((const float4*)X, (__half2*)xh, (int)(nXY / 4));
    cvt_half<<<2048, 256>>>((const float4*)Y, (__half2*)yh, (int)(nXY / 4));
    trans_half<<<dim3(H / 32, F / 32, 1), 256>>>(K, kth, F, H, 0, 0);    // kth[H,F]
    trans_half<<<dim3(H / 32, F / 32, 1), 256>>>(Q, qth, F, H, 0, 0);    // qth[H,F]
    trans_half<<<dim3(F / 32, S / 32, B), 256>>>(Y, yth, S, F, sY, sYT); // yth[F,S]

    // 2) projections (f32 out)
    gemm_h<<<dim3(H / 128, (B * S) / 128, 1), 256, GSMEM>>>(
        yh, kth, keysf, B * S, H, F, 0, 0, 0);
    gemm_h<<<dim3(H / 128, (B * S) / 128, 1), 256, GSMEM>>>(
        xh, qth, queriesf, B * S, H, F, 0, 0, 0);

    // 3) layernorms (f32 in -> half out)
    layernorm_kernel<<<B * S, 256>>>(keysf, keysh, g1, b1);
    layernorm_kernel<<<B * S, 256>>>(queriesf, queriesh, g2, b2);

    // 4) logits: alpha[b] = queries[b] @ keys[b]^T  (f32 out)
    gemm_h<<<dim3(S / 128, S / 128, B), 256, GSMEM>>>(
        queriesh, keysh, alphaf, S, S, H, sQK, sQK, sAL);

    // 5) softmax (f32 in -> half out, applies 1/H)
    softmax_kernel<<<B * S, 256>>>(alphaf, alphah);

    // 6) out[b] = alphah[b] @ yth[b]^T  (f32 out)
    gemm_h<<<dim3(F / 128, S / 128, B), 256, GSMEM>>>(
        alphah, yth, out, S, F, S, sAL, sYT, sY);
}

// round 6
// speedup vs baseline: 7.4174x; 1.0622x over previous
#include <cuda_runtime.h>
#include <cuda_fp16.h>
#include <cstdint>

// ----------------------------------------------------------------------------
// Attention_53944789237811  (round 6: fp16 mma + softmax fused into epilogues)
//   keys    = LayerNorm(Y @ K) * g1 + b1          [B,S,H]
//   queries = LayerNorm(X @ Q) * g2 + b2          [B,S,H]
//   alpha   = softmax(queries @ keys^T / H)       [B,S,S]
//   out     = alpha @ Y                           [B,S,F]
// B=8, S=2048, F=H=1024.
// Logits are tiny (|x| <~ 0.2), so exp needs no max-subtraction:
//   QK epilogue writes p = exp(logit/H) as half + accumulates row sums;
//   PV epilogue divides by the row sum. Softmax kernel eliminated.
// ----------------------------------------------------------------------------

// ---------------- scratch (device globals; no cudaMalloc allowed) ------------
__device__ __half g_xh      [8ull * 2048 * 1024];   //  32 MB  X (half)
__device__ __half g_yh      [8ull * 2048 * 1024];   //  32 MB  Y (half)
__device__ __half g_kth     [1024ull * 1024];       //   2 MB  K^T
__device__ __half g_qth     [1024ull * 1024];       //   2 MB  Q^T
__device__ __half g_yth     [8ull * 1024 * 2048];   //  32 MB  Y^T
__device__ __half g_keysh   [8ull * 2048 * 1024];   //  32 MB  proj -> LN'd keys
__device__ __half g_queriesh[8ull * 2048 * 1024];   //  32 MB  proj -> LN'd queries
__device__ __half g_alphah  [8ull * 2048 * 2048];   //  64 MB  exp(logits)
__device__ float  g_rowsum  [8ull * 2048];          //  64 KB  softmax denominators

// ---------------- helpers ------------------------------------------------------
__device__ __forceinline__ uint32_t smem_u32(const void* p) {
    uint32_t a;
    asm("{ .reg .u64 t; cvta.to.shared.u64 t, %1; cvt.u32.u64 %0, t; }"
        : "=r"(a) : "l"(p));
    return a;
}

__device__ __forceinline__ void mma_fp16(float* c, const uint32_t* a, const uint32_t* b) {
    asm volatile(
        "mma.sync.aligned.m16n8k16.row.col.f32.f16.f16.f32 "
        "{%0,%1,%2,%3}, {%4,%5,%6,%7}, {%8,%9}, {%0,%1,%2,%3};\n"
        : "+f"(c[0]), "+f"(c[1]), "+f"(c[2]), "+f"(c[3])
        : "r"(a[0]), "r"(a[1]), "r"(a[2]), "r"(a[3]), "r"(b[0]), "r"(b[1]));
}

__device__ __forceinline__ void ldsm4(uint32_t* r, uint32_t addr) {
    asm volatile("ldmatrix.sync.aligned.m8n8.x4.shared.b16 {%0,%1,%2,%3}, [%4];"
                 : "=r"(r[0]), "=r"(r[1]), "=r"(r[2]), "=r"(r[3]) : "r"(addr));
}

__device__ __forceinline__ void cp16(uint32_t dst, const void* src) {
    asm volatile("cp.async.cg.shared.global [%0], [%1], 16;"
                 :: "r"(dst), "l"(src) : "memory");
}
#define CP_COMMIT() asm volatile("cp.async.commit_group;" ::: "memory")

#define SWZ(o) ((o) ^ ((((uint32_t)(o)) >> 3) & 0x70u))

// ---------------- fp16 tensor GEMM ---------------------------------------------
// C = A[M,K] * B[N,K]^T.  A,B fp16 row-major. CTA tile 128x128, BK=64,
// 3-stage cp.async, 256 threads, warp tile 32x64, ldmatrix.x4 loads.
// EPI 0: C half (plain convert)            [projections]
// EPI 1: C half = exp(acc/1024), + rowsum  [QK logits]
// EPI 2: C f32  = acc / rowsum[row]        [PV output]
#define TILEB  16384
#define STAGEB 32768
#define GSMEM  (3 * STAGEB)   // 96 KB

__device__ __forceinline__ void load_stage(
    const __half* A, const __half* B, int Kd, int row0, int col0, int kk,
    uint32_t abuf, uint32_t bbuf, int tid)
{
#pragma unroll
    for (int i = 0; i < 4; i++) {
        int ch = tid + i * 256;
        int r = ch >> 3, c = ch & 7;
        cp16(abuf + SWZ(r * 128 + c * 16),
             A + (long long)(row0 + r) * Kd + kk + c * 8);
    }
#pragma unroll
    for (int i = 0; i < 4; i++) {
        int ch = tid + i * 256;
        int r = ch >> 3, c = ch & 7;
        cp16(bbuf + SWZ(r * 128 + c * 16),
             B + (long long)(col0 + r) * Kd + kk + c * 8);
    }
    CP_COMMIT();
}

template <int EPI>
__global__ __launch_bounds__(256, 2)
void gemm_h(const __half* __restrict__ A, const __half* __restrict__ B,
            void* __restrict__ Cv, float* __restrict__ rowsum,
            int M, int N, int Kd,
            long long sA, long long sB, long long sC, long long sR)
{
    extern __shared__ __align__(1024) char smem[];
    A += (long long)blockIdx.z * sA;
    B += (long long)blockIdx.z * sB;
    rowsum += (long long)blockIdx.z * sR;

    const uint32_t sbase = smem_u32(smem);
    const int tid  = threadIdx.x;
    const int warp = tid >> 5;
    const int lane = tid & 31;
    const int gid  = lane >> 2;
    const int tig  = lane & 3;
    const int warp_m = warp & 3;
    const int warp_n = warp >> 2;
    const int row0 = blockIdx.y * 128;
    const int col0 = blockIdx.x * 128;

    const int l7 = lane & 7;
    uint32_t aoff[2], axm[2];
#pragma unroll
    for (int mt = 0; mt < 2; mt++) {
        int row = warp_m * 32 + mt * 16 + ((lane >> 3) & 1) * 8 + l7;
        aoff[mt] = (uint32_t)row * 128;
        axm[mt]  = (uint32_t)(row & 7) * 16;
    }
    const uint32_t aq = (uint32_t)((lane >> 4) & 1) * 16;
    uint32_t boff[4], bxm[4];
#pragma unroll
    for (int p = 0; p < 4; p++) {
        int row = warp_n * 64 + p * 16 + ((lane >> 4) & 1) * 8 + l7;
        boff[p] = (uint32_t)row * 128;
        bxm[p]  = (uint32_t)(row & 7) * 16;
    }
    const uint32_t bq = (uint32_t)((lane >> 3) & 1) * 16;

    float acc[2][8][4];
#pragma unroll
    for (int i = 0; i < 2; i++)
#pragma unroll
        for (int j = 0; j < 8; j++)
#pragma unroll
            for (int l = 0; l < 4; l++) acc[i][j][l] = 0.f;

    const int nst = Kd / 64;

    load_stage(A, B, Kd, row0, col0, 0,  sbase, sbase + TILEB, tid);
    load_stage(A, B, Kd, row0, col0, 64, sbase + STAGEB, sbase + STAGEB + TILEB, tid);

    for (int s = 0; s < nst; s++) {
        if (s + 1 < nst)
            asm volatile("cp.async.wait_group 1;" ::: "memory");
        else
            asm volatile("cp.async.wait_group 0;" ::: "memory");
        __syncthreads();

        const uint32_t abuf = sbase + (s % 3) * STAGEB;
        const uint32_t bbuf = abuf + TILEB;

#pragma unroll
        for (int kg = 0; kg < 4; kg++) {
            uint32_t a[2][4], b[4][4];
#pragma unroll
            for (int mt = 0; mt < 2; mt++)
                ldsm4(a[mt], abuf + aoff[mt] + (((uint32_t)kg * 32 + aq) ^ axm[mt]));
#pragma unroll
            for (int p = 0; p < 4; p++)
                ldsm4(b[p], bbuf + boff[p] + (((uint32_t)kg * 32 + bq) ^ bxm[p]));
#pragma unroll
            for (int mt = 0; mt < 2; mt++)
#pragma unroll
                for (int nt = 0; nt < 8; nt++)
                    mma_fp16(acc[mt][nt], a[mt], &b[nt >> 1][(nt & 1) * 2]);
        }

        if (s + 2 < nst) {
            int t = s + 2;
            const uint32_t nabuf = sbase + (t % 3) * STAGEB;
            load_stage(A, B, Kd, row0, col0, t * 64, nabuf, nabuf + TILEB, tid);
        }
    }

    // ---- epilogue ----
    if (EPI == 0) {
        __half* C = (__half*)Cv + (long long)blockIdx.z * sC;
#pragma unroll
        for (int mt = 0; mt < 2; mt++) {
            int r = row0 + warp_m * 32 + mt * 16 + gid;
#pragma unroll
            for (int nt = 0; nt < 8; nt++) {
                int c = col0 + warp_n * 64 + nt * 8 + tig * 2;
                *(__half2*)(C + (long long)r * N + c) =
                    __floats2half2_rn(acc[mt][nt][0], acc[mt][nt][1]);
                *(__half2*)(C + (long long)(r + 8) * N + c) =
                    __floats2half2_rn(acc[mt][nt][2], acc[mt][nt][3]);
            }
        }
    } else if (EPI == 1) {
        __half* C = (__half*)Cv + (long long)blockIdx.z * sC;
        const float sc = 1.4426950408889634f / 1024.0f;  // log2(e)/H
#pragma unroll
        for (int mt = 0; mt < 2; mt++) {
            int r = row0 + warp_m * 32 + mt * 16 + gid;
            float rs0 = 0.f, rs1 = 0.f;
#pragma unroll
            for (int nt = 0; nt < 8; nt++) {
                int c = col0 + warp_n * 64 + nt * 8 + tig * 2;
                float p0 = exp2f(acc[mt][nt][0] * sc);
                float p1 = exp2f(acc[mt][nt][1] * sc);
                float p2 = exp2f(acc[mt][nt][2] * sc);
                float p3 = exp2f(acc[mt][nt][3] * sc);
                *(__half2*)(C + (long long)r * N + c)       = __floats2half2_rn(p0, p1);
                *(__half2*)(C + (long long)(r + 8) * N + c) = __floats2half2_rn(p2, p3);
                rs0 += p0 + p1;
                rs1 += p2 + p3;
            }
            rs0 += __shfl_xor_sync(0xffffffffu, rs0, 1);
            rs0 += __shfl_xor_sync(0xffffffffu, rs0, 2);
            rs1 += __shfl_xor_sync(0xffffffffu, rs1, 1);
            rs1 += __shfl_xor_sync(0xffffffffu, rs1, 2);
            if (tig == 0) {
                atomicAdd(&rowsum[r], rs0);
                atomicAdd(&rowsum[r + 8], rs1);
            }
        }
    } else {
        float* C = (float*)Cv + (long long)blockIdx.z * sC;
#pragma unroll
        for (int mt = 0; mt < 2; mt++) {
            int r = row0 + warp_m * 32 + mt * 16 + gid;
            const float i0 = 1.0f / rowsum[r];
            const float i1 = 1.0f / rowsum[r + 8];
#pragma unroll
            for (int nt = 0; nt < 8; nt++) {
                int c = col0 + warp_n * 64 + nt * 8 + tig * 2;
                *(float2*)(C + (long long)r * N + c) =
                    make_float2(acc[mt][nt][0] * i0, acc[mt][nt][1] * i0);
                *(float2*)(C + (long long)(r + 8) * N + c) =
                    make_float2(acc[mt][nt][2] * i1, acc[mt][nt][3] * i1);
            }
        }
    }
}

// ---------------- pre/aux kernels ------------------------------------------------
__global__ __launch_bounds__(256) void cvt_half(const float4* __restrict__ in,
                                                __half2* __restrict__ out, int n4)
{
    int i = blockIdx.x * 256 + threadIdx.x;
    int stride = gridDim.x * 256;
    for (; i < n4; i += stride) {
        float4 v = in[i];
        out[i * 2 + 0] = __floats2half2_rn(v.x, v.y);
        out[i * 2 + 1] = __floats2half2_rn(v.z, v.w);
    }
}

__global__ __launch_bounds__(256) void trans_half(
    const float* __restrict__ in, __half* __restrict__ out,
    int R, int C, long long sIn, long long sOut)
{
    in  += (long long)blockIdx.z * sIn;
    out += (long long)blockIdx.z * sOut;
    __shared__ float t[32][33];
    const int r0 = blockIdx.y * 32, c0 = blockIdx.x * 32;
    const int tx = threadIdx.x & 31, ty = threadIdx.x >> 5;
#pragma unroll
    for (int i = 0; i < 32; i += 8)
        t[ty + i][tx] = in[(long long)(r0 + ty + i) * C + c0 + tx];
    __syncthreads();
#pragma unroll
    for (int i = 0; i < 32; i += 8)
        out[(long long)(c0 + ty + i) * R + r0 + tx] = __float2half_rn(t[tx][ty + i]);
}

__global__ __launch_bounds__(256) void clear_f32(float* __restrict__ p, int n)
{
    int i = blockIdx.x * 256 + threadIdx.x;
    if (i < n) p[i] = 0.f;
}

// ---------------- layernorm: half in-place (f32 math) ---------------------------
__global__ __launch_bounds__(256) void layernorm_kernel(
    __half* __restrict__ data,
    const float* __restrict__ gamma, const float* __restrict__ beta)
{
    const int H = 1024;
    __half* row = data + (long long)blockIdx.x * H;
    const int t = threadIdx.x;
    const int lane = t & 31, wid = t >> 5;

    float v[4];
    float s = 0.f, q = 0.f;
#pragma unroll
    for (int i = 0; i < 4; i++) {
        v[i] = __half2float(row[t + i * 256]);
        s += v[i];
        q += v[i] * v[i];
    }
#pragma unroll
    for (int o = 16; o > 0; o >>= 1) {
        s += __shfl_xor_sync(0xffffffffu, s, o);
        q += __shfl_xor_sync(0xffffffffu, q, o);
    }
    __shared__ float ss[8], sq[8];
    if (lane == 0) { ss[wid] = s; sq[wid] = q; }
    __syncthreads();
    if (wid == 0) {
        float s2 = (lane < 8) ? ss[lane] : 0.f;
        float q2 = (lane < 8) ? sq[lane] : 0.f;
#pragma unroll
        for (int o = 4; o > 0; o >>= 1) {
            s2 += __shfl_xor_sync(0xffffffffu, s2, o);
            q2 += __shfl_xor_sync(0xffffffffu, q2, o);
        }
        if (lane == 0) { ss[0] = s2; sq[0] = q2; }
    }
    __syncthreads();
    const float mu  = ss[0] * (1.f / 1024.f);
    const float var = sq[0] * (1.f / 1024.f) - mu * mu;
    const float inv = rsqrtf(var + 1e-5f);
#pragma unroll
    for (int i = 0; i < 4; i++) {
        const int c = t + i * 256;
        row[c] = __float2half_rn((v[i] - mu) * inv * gamma[c] + beta[c]);
    }
}

// ---------------- kernel_launch --------------------------------------------------
extern "C" void kernel_launch(void* const* d_in, const int* in_sizes, int n_in,
                              void* d_out, int out_size)
{
    const float* X  = (const float*)d_in[0];
    const float* Y  = (const float*)d_in[1];
    const float* K  = (const float*)d_in[2];
    const float* Q  = (const float*)d_in[3];
    const float* g1 = (const float*)d_in[4];
    const float* b1 = (const float*)d_in[5];
    const float* g2 = (const float*)d_in[6];
    const float* b2 = (const float*)d_in[7];
    float* out = (float*)d_out;

    __half *xh, *yh, *kth, *qth, *yth, *keysh, *queriesh, *alphah;
    float* rowsum;
    cudaGetSymbolAddress((void**)&xh,       g_xh);
    cudaGetSymbolAddress((void**)&yh,       g_yh);
    cudaGetSymbolAddress((void**)&kth,      g_kth);
    cudaGetSymbolAddress((void**)&qth,      g_qth);
    cudaGetSymbolAddress((void**)&yth,      g_yth);
    cudaGetSymbolAddress((void**)&keysh,    g_keysh);
    cudaGetSymbolAddress((void**)&queriesh, g_queriesh);
    cudaGetSymbolAddress((void**)&alphah,   g_alphah);
    cudaGetSymbolAddress((void**)&rowsum,   g_rowsum);

    cudaFuncSetAttribute(gemm_h<0>, cudaFuncAttributeMaxDynamicSharedMemorySize, GSMEM);
    cudaFuncSetAttribute(gemm_h<1>, cudaFuncAttributeMaxDynamicSharedMemorySize, GSMEM);
    cudaFuncSetAttribute(gemm_h<2>, cudaFuncAttributeMaxDynamicSharedMemorySize, GSMEM);

    const int B = 8, S = 2048, F = 1024, H = 1024;
    const long long nXY = (long long)B * S * F;
    const long long sQK = (long long)S * H;
    const long long sAL = (long long)S * S;
    const long long sY  = (long long)S * F;
    const long long sYT = (long long)F * S;

    // 1) fp16 conversions + transposes
    cvt_half<<<2048, 256>>>((const float4*)X, (__half2*)xh, (int)(nXY / 4));
    cvt_half<<<2048, 256>>>((const float4*)Y, (__half2*)yh, (int)(nXY / 4));
    trans_half<<<dim3(H / 32, F / 32, 1), 256>>>(K, kth, F, H, 0, 0);
    trans_half<<<dim3(H / 32, F / 32, 1), 256>>>(Q, qth, F, H, 0, 0);
    trans_half<<<dim3(F / 32, S / 32, B), 256>>>(Y, yth, S, F, sY, sYT);

    // 2) projections (half out, in-place LN after)
    gemm_h<0><<<dim3(H / 128, (B * S) / 128, 1), 256, GSMEM>>>(
        yh, kth, keysh, nullptr, B * S, H, F, 0, 0, 0, 0);
    gemm_h<0><<<dim3(H / 128, (B * S) / 128, 1), 256, GSMEM>>>(
        xh, qth, queriesh, nullptr, B * S, H, F, 0, 0, 0, 0);

    // 3) layernorms (in-place on half)
    layernorm_kernel<<<B * S, 256>>>(keysh, g1, b1);
    layernorm_kernel<<<B * S, 256>>>(queriesh, g2, b2);

    // 4) clear softmax denominators
    clear_f32<<<(B * S + 255) / 256, 256>>>(rowsum, B * S);

    // 5) QK logits + fused exp + row sums: alphah = exp(q.k/H)
    gemm_h<1><<<dim3(S / 128, S / 128, B), 256, GSMEM>>>(
        queriesh, keysh, alphah, rowsum, S, S, H, sQK, sQK, sAL, S);

    // 6) PV + fused division: out = (alphah @ yth^T) / rowsum
    gemm_h<2><<<dim3(F / 128, S / 128, B), 256, GSMEM>>>(
        alphah, yth, out, rowsum, S, F, S, sAL, sYT, sY, S);
}